// round 1
// baseline (speedup 1.0000x reference)
#include <cuda_runtime.h>
#include <cuda_bf16.h>

#define EPS 1e-9f
#define BATCH 128
#define NN 400
#define HH 128
#define NSQ (NN * NN)           // 160000
#define KTOP 32000

// ---------------- scratch (static device memory; no allocs allowed) ----------
__device__ float g_xf[BATCH * NSQ];          // xf, later x2 (in place)
__device__ float g_delta[BATCH * NSQ];       // delta, later A / An (in place)
__device__ float g_out1[BATCH * HH * NN];    // out1 [B,H,N], later Y2 [B,N,H]
__device__ float g_out2a[BATCH * HH * HH];   // [B,H,H]
__device__ float g_out2[BATCH * HH * NN];    // out2 [B,H,N], later Y1 [B,N,H]
__device__ float g_h1[BATCH * NN * HH];      // h1 [B,N,H]
__device__ unsigned long long g_thresh[BATCH];
__device__ float g_dinv[BATCH * NN];
__device__ float g_rs[BATCH * NN];

// ---------------- elementwise: fisher transform + normalize ------------------
__global__ void fisher_k(const float* __restrict__ x, float* __restrict__ xf) {
    int r = blockIdx.x * 256 + threadIdx.x;            // 0..159999
    int b = blockIdx.y;
    size_t base = (size_t)b * NSQ;
    float x00 = x[base];
    float d = 0.5f * logf((1.f + x00 + EPS) / (1.f - x00 + EPS));
    float v = x[base + r];
    float f = 0.5f * logf((1.f + v + EPS) / (1.f - v + EPS));
    xf[base + r] = f / d;
}

// ---------------- x2 = xf + 0.5*(delta + delta^T) * (1-eye), in place --------
__global__ void sym_k(float* __restrict__ xf, const float* __restrict__ delta) {
    int b = blockIdx.z;
    int j0 = blockIdx.x * 32, i0 = blockIdx.y * 32;
    int tx = threadIdx.x, ty = threadIdx.y;
    __shared__ float sh[32][33];
    size_t base = (size_t)b * NSQ;
    // load delta rows [j0, j0+32), cols [i0, i0+32) coalesced
    int lr = j0 + ty, lc = i0 + tx;
    sh[ty][tx] = (lr < NN && lc < NN) ? delta[base + (size_t)lr * NN + lc] : 0.f;
    __syncthreads();
    int i = i0 + ty, j = j0 + tx;
    if (i < NN && j < NN) {
        size_t idx = base + (size_t)i * NN + j;
        float v = xf[idx];
        if (i != j) v += 0.5f * (delta[idx] + sh[tx][ty]);   // sh[tx][ty] = delta[j][i]
        xf[idx] = v;
    }
}

// ---------------- exact k-th largest via 64-bit key radix select -------------
__device__ __forceinline__ unsigned long long make_key(float v, unsigned t) {
    unsigned u = __float_as_uint(v);
    unsigned k32 = (u & 0x80000000u) ? ~u : (u | 0x80000000u);
    return ((unsigned long long)k32 << 32) | (unsigned long long)(~t);
}

__global__ void radix_select_k(const float* __restrict__ x2,
                               unsigned long long* __restrict__ thresh) {
    const int b = blockIdx.x;
    const float* xp = x2 + (size_t)b * NSQ;
    __shared__ unsigned hist[16][256];
    __shared__ unsigned total[256];
    __shared__ unsigned long long s_prefix;
    __shared__ unsigned s_remaining;
    int tid = threadIdx.x;          // 512 threads = 16 warps
    int wid = tid >> 5, lane = tid & 31;
    if (tid == 0) { s_prefix = 0ull; s_remaining = KTOP; }
    __syncthreads();

    for (int pass = 0; pass < 8; pass++) {
        int shift = 56 - 8 * pass;
        for (int i = tid; i < 16 * 256; i += 512) ((unsigned*)hist)[i] = 0;
        __syncthreads();
        unsigned long long prefix = s_prefix;
        int hs = shift + 8;
        for (int t = tid; t < 160256; t += 512) {
            bool inr = t < NSQ;
            unsigned long long key = inr ? make_key(xp[t], (unsigned)t) : 0ull;
            bool ok = inr && ((hs >= 64) || ((key >> hs) == (prefix >> hs)));
            unsigned bin = (unsigned)((key >> shift) & 255);
            unsigned active = __ballot_sync(0xffffffffu, ok);
            if (ok) {
                unsigned peers = __match_any_sync(active, bin);
                int leader = __ffs(peers) - 1;
                if (lane == leader) atomicAdd(&hist[wid][bin], __popc(peers));
            }
        }
        __syncthreads();
        for (int i = tid; i < 256; i += 512) {
            unsigned s = 0;
            #pragma unroll
            for (int w = 0; w < 16; w++) s += hist[w][i];
            total[i] = s;
        }
        __syncthreads();
        if (tid == 0) {
            unsigned rem = s_remaining, cum = 0;
            int chosen = 0;
            for (int bin = 255; bin >= 0; bin--) {
                unsigned c = total[bin];
                if (cum + c >= rem) { chosen = bin; s_remaining = rem - cum; break; }
                cum += c;
            }
            s_prefix |= ((unsigned long long)chosen << shift);
        }
        __syncthreads();
    }
    if (tid == 0) thresh[b] = s_prefix;   // exact k-th largest (value, index) key
}

// ---------------- A = x2 * mask (+ self loops where diag==0) ----------------
__global__ void mask_k(const float* __restrict__ x2,
                       const unsigned long long* __restrict__ thresh,
                       float* __restrict__ A) {
    int r = blockIdx.x * 256 + threadIdx.x;
    int b = blockIdx.y;
    size_t idx = (size_t)b * NSQ + r;
    float v = x2[idx];
    unsigned long long key = make_key(v, (unsigned)r);
    float a = (key >= thresh[b]) ? v : 0.f;
    int i = r / NN, j = r - i * NN;
    if (i == j && a == 0.f) a = 1.f;
    A[idx] = a;
}

// ---------------- column degree -> dinv --------------------------------------
__global__ void deg_k(const float* __restrict__ A, float* __restrict__ dinv) {
    int b = blockIdx.x;
    int j = threadIdx.x;
    if (j >= NN) return;
    const float* Ab = A + (size_t)b * NSQ;
    float acc = 0.f;
    for (int i = 0; i < NN; i++) acc += Ab[(size_t)i * NN + j];
    float dv = rsqrtf(acc);
    if (isinf(dv)) dv = 0.f;
    dinv[b * NN + j] = dv;
}

// ---------------- An = dinv[i]*A*dinv[j] in place; rs[i] = sum_j An[i,j]/N ---
__global__ void an_k(float* __restrict__ A, const float* __restrict__ dinv,
                     float* __restrict__ rs) {
    int i = blockIdx.x, b = blockIdx.y;
    int tid = threadIdx.x;     // 128
    const float* dv = dinv + b * NN;
    float* row = A + (size_t)b * NSQ + (size_t)i * NN;
    float di = dv[i];
    float acc = 0.f;
    for (int j = tid; j < NN; j += 128) {
        float v = row[j] * di * dv[j];
        row[j] = v;
        acc += v;
    }
    __shared__ float sb[128];
    sb[tid] = acc;
    __syncthreads();
    for (int s = 64; s > 0; s >>= 1) {
        if (tid < s) sb[tid] += sb[tid + s];
        __syncthreads();
    }
    if (tid == 0) rs[b * NN + i] = sb[0] * (1.f / NN);
}

// ---------------- generic batched SMEM-tiled GEMM ----------------------------
// C[M,N] = A(MxK) @ B(KxN); TRANSA: A stored [K][M]; EPI 0=none,1=relu,2=relu+skip
// TRANSOUT: store C at [n*ldc + m]
#define BM 64
#define BN 64
#define BK 16

template<int TRANSA, int EPI, int TRANSOUT>
__global__ void gemm_k(const float* __restrict__ A, size_t strideA, int lda,
                       const float* __restrict__ Bm, size_t strideB, int ldb,
                       const float* __restrict__ bias,
                       const float* __restrict__ skip, size_t strideS, int lds,
                       float* __restrict__ C, size_t strideC, int ldc,
                       int M, int N, int K) {
    int b = blockIdx.z;
    A += (size_t)b * strideA;
    Bm += (size_t)b * strideB;
    if (EPI == 2) skip += (size_t)b * strideS;
    C += (size_t)b * strideC;

    int n0 = blockIdx.x * BN;
    int m0 = blockIdx.y * BM;

    __shared__ float As[BK][BM + 1];
    __shared__ float Bs[BK][BN];

    int tid = threadIdx.x;              // 256
    int tm = (tid / 16) * 4;
    int tn = (tid % 16) * 4;

    float acc[4][4] = {};

    for (int k0 = 0; k0 < K; k0 += BK) {
        if (TRANSA) {
            int kk = tid / 64, mm = tid % 64;
            #pragma unroll
            for (int r = 0; r < 4; r++) {
                int k = kk + r * 4;
                int m = m0 + mm;
                As[k][mm] = (m < M) ? A[(size_t)(k0 + k) * lda + m] : 0.f;
            }
        } else {
            int row = tid / 16, col = tid % 16;
            #pragma unroll
            for (int r = 0; r < 4; r++) {
                int m = m0 + row + r * 16;
                As[col][row + r * 16] = (m < M) ? A[(size_t)m * lda + (k0 + col)] : 0.f;
            }
        }
        {
            int kk = tid / 64, nn = tid % 64;
            #pragma unroll
            for (int r = 0; r < 4; r++) {
                int k = kk + r * 4;
                int n = n0 + nn;
                Bs[k][nn] = (n < N) ? Bm[(size_t)(k0 + k) * ldb + n] : 0.f;
            }
        }
        __syncthreads();
        #pragma unroll
        for (int k = 0; k < BK; k++) {
            float a[4], bv[4];
            #pragma unroll
            for (int i = 0; i < 4; i++) a[i] = As[k][tm + i];
            #pragma unroll
            for (int j = 0; j < 4; j++) bv[j] = Bs[k][tn + j];
            #pragma unroll
            for (int i = 0; i < 4; i++)
                #pragma unroll
                for (int j = 0; j < 4; j++)
                    acc[i][j] += a[i] * bv[j];
        }
        __syncthreads();
    }

    #pragma unroll
    for (int i = 0; i < 4; i++) {
        int m = m0 + tm + i;
        if (m >= M) continue;
        #pragma unroll
        for (int j = 0; j < 4; j++) {
            int n = n0 + tn + j;
            if (n >= N) continue;
            float v = acc[i][j];
            if (bias) v += bias[n];
            if (EPI == 2) v += skip[(size_t)m * lds + n];
            if (EPI >= 1) v = fmaxf(v, 0.f);
            if (TRANSOUT) C[(size_t)n * ldc + m] = v;
            else          C[(size_t)m * ldc + n] = v;
        }
    }
}

// ---------------- head: pooled = rs . Y2 + b; out = relu(pooled) @ fc --------
__global__ void head_k(const float* __restrict__ Y2, const float* __restrict__ rs,
                       const float* __restrict__ b2, const float* __restrict__ fcw,
                       const float* __restrict__ fcb, float* __restrict__ out) {
    int b = blockIdx.x;
    int f = threadIdx.x;                // 128
    const float* Y = Y2 + (size_t)b * (NN * HH);
    const float* r = rs + b * NN;
    float acc = 0.f;
    for (int i = 0; i < NN; i++) acc += r[i] * Y[(size_t)i * HH + f];
    acc += b2[f];
    float pf = fmaxf(acc, 0.f);
    __shared__ float sp[HH];
    sp[f] = pf;
    __syncthreads();
    if (f < 2) {
        float o = fcb[f];
        for (int q = 0; q < HH; q++) o += sp[q] * fcw[q * 2 + f];
        out[b * 2 + f] = o;
    }
}

// -----------------------------------------------------------------------------
extern "C" void kernel_launch(void* const* d_in, const int* in_sizes, int n_in,
                              void* d_out, int out_size) {
    const float* x      = (const float*)d_in[0];
    // d_in[1] = slength (unused)
    const float* enc1_w = (const float*)d_in[2];
    const float* enc1_b = (const float*)d_in[3];
    const float* enc2_w = (const float*)d_in[4];
    const float* enc2_b = (const float*)d_in[5];
    const float* dec2_w = (const float*)d_in[6];
    const float* dec2_b = (const float*)d_in[7];
    const float* dec1_w = (const float*)d_in[8];
    const float* dec1_b = (const float*)d_in[9];
    const float* gcn1_w = (const float*)d_in[10];
    const float* gcn1_b = (const float*)d_in[11];
    const float* gcn2_w = (const float*)d_in[12];
    const float* gcn2_b = (const float*)d_in[13];
    const float* fc_w   = (const float*)d_in[14];
    const float* fc_b   = (const float*)d_in[15];
    float* out = (float*)d_out;

    float *xf, *delta, *out1, *out2a, *out2, *h1, *dinv, *rs;
    unsigned long long* thresh;
    cudaGetSymbolAddress((void**)&xf, g_xf);
    cudaGetSymbolAddress((void**)&delta, g_delta);
    cudaGetSymbolAddress((void**)&out1, g_out1);
    cudaGetSymbolAddress((void**)&out2a, g_out2a);
    cudaGetSymbolAddress((void**)&out2, g_out2);
    cudaGetSymbolAddress((void**)&h1, g_h1);
    cudaGetSymbolAddress((void**)&thresh, g_thresh);
    cudaGetSymbolAddress((void**)&dinv, g_dinv);
    cudaGetSymbolAddress((void**)&rs, g_rs);

    const size_t S_NN = (size_t)NSQ;          // 160000
    const size_t S_HN = (size_t)HH * NN;      // 51200
    const size_t S_HH = (size_t)HH * HH;      // 16384

    // 0) fisher transform + normalize
    fisher_k<<<dim3(625, BATCH), 256>>>(x, xf);

    // 1) out1[b,h,i] = relu(xf @ enc1_w + b)  (transposed store)
    gemm_k<0, 1, 1><<<dim3(2, 7, BATCH), 256>>>(
        xf, S_NN, NN, enc1_w, 0, HH, enc1_b, nullptr, 0, 0,
        out1, S_HN, NN, NN, HH, NN);

    // 2) out2a = relu(out1 @ enc2_w + b)   [B,H,H]
    gemm_k<0, 1, 0><<<dim3(2, 2, BATCH), 256>>>(
        out1, S_HN, NN, enc2_w, 0, HH, enc2_b, nullptr, 0, 0,
        out2a, S_HH, HH, HH, HH, NN);

    // 3) out2 = relu(out2a @ dec2_w + b + out1)  [B,H,N]
    gemm_k<0, 2, 0><<<dim3(7, 2, BATCH), 256>>>(
        out2a, S_HH, HH, dec2_w, 0, NN, dec2_b, out1, S_HN, NN,
        out2, S_HN, NN, HH, NN, HH);

    // 4) delta = out2^T @ dec1_w + b  [B,N,N]
    gemm_k<1, 0, 0><<<dim3(7, 7, BATCH), 256>>>(
        out2, S_HN, NN, dec1_w, 0, NN, dec1_b, nullptr, 0, 0,
        delta, S_NN, NN, NN, NN, HH);

    // 5) x2 = xf + 0.5*(delta + delta^T)*(1-eye)  (in place in xf)
    sym_k<<<dim3(13, 13, BATCH), dim3(32, 32)>>>(xf, delta);

    // 6) per-batch exact top-k threshold key
    radix_select_k<<<BATCH, 512>>>(xf, thresh);

    // 7) A = masked x2 (+ self loops), into delta buffer
    mask_k<<<dim3(625, BATCH), 256>>>(xf, thresh, delta);

    // 8) column degrees -> dinv
    deg_k<<<BATCH, 512>>>(delta, dinv);

    // 9) An = dinv_i * A * dinv_j in place; rs = row means
    an_k<<<dim3(NN, BATCH), 128>>>(delta, dinv, rs);

    // 10) Y1 = x2 @ gcn1_w   [B,N,H]  (into out2 buffer)
    gemm_k<0, 0, 0><<<dim3(2, 7, BATCH), 256>>>(
        xf, S_NN, NN, gcn1_w, 0, HH, nullptr, nullptr, 0, 0,
        out2, S_HN, HH, NN, HH, NN);

    // 11) h1 = relu(An^T @ Y1 + gcn1_b)  [B,N,H]
    gemm_k<1, 1, 0><<<dim3(2, 7, BATCH), 256>>>(
        delta, S_NN, NN, out2, S_HN, HH, gcn1_b, nullptr, 0, 0,
        h1, S_HN, HH, NN, HH, NN);

    // 12) Y2 = h1 @ gcn2_w  [B,N,H] (into out1 buffer)
    gemm_k<0, 0, 0><<<dim3(2, 7, BATCH), 256>>>(
        h1, S_HN, HH, gcn2_w, 0, HH, nullptr, nullptr, 0, 0,
        out1, S_HN, HH, NN, HH, HH);

    // 13) pooled/head: mean_j(An^T Y2 + b2) folded to rs . Y2 + b2, then fc
    head_k<<<BATCH, HH>>>(out1, rs, gcn2_b, fc_w, fc_b, out);
}

// round 2
// speedup vs baseline: 1.0086x; 1.0086x over previous
#include <cuda_runtime.h>
#include <cuda_bf16.h>

#define EPS 1e-9f
#define BATCH 128
#define NN 400
#define HH 128
#define NSQ (NN * NN)           // 160000
#define KTOP 32000

// ---------------- scratch (static device memory; no allocs allowed) ----------
__device__ float g_xf[BATCH * NSQ];          // xf, later x2 (in place)
__device__ float g_delta[BATCH * NSQ];       // delta, later A / An (in place)
__device__ float g_out1[BATCH * HH * NN];    // out1 [B,H,N], later Y2 [B,N,H]
__device__ float g_out2a[BATCH * HH * HH];   // [B,H,H]
__device__ float g_out2[BATCH * HH * NN];    // out2 [B,H,N], later Y1 [B,N,H]
__device__ float g_h1[BATCH * NN * HH];      // h1 [B,N,H]
__device__ unsigned long long g_thresh[BATCH];
__device__ float g_dinv[BATCH * NN];
__device__ float g_rs[BATCH * NN];

// ---------------- elementwise: fisher transform + normalize ------------------
__global__ void fisher_k(const float* __restrict__ x, float* __restrict__ xf) {
    int r = blockIdx.x * 256 + threadIdx.x;            // 0..159999
    int b = blockIdx.y;
    size_t base = (size_t)b * NSQ;
    float x00 = x[base];
    float d = 0.5f * logf((1.f + x00 + EPS) / (1.f - x00 + EPS));
    float v = x[base + r];
    float f = 0.5f * logf((1.f + v + EPS) / (1.f - v + EPS));
    xf[base + r] = f / d;
}

// ---------------- x2 = xf + 0.5*(delta + delta^T) * (1-eye), in place --------
__global__ void sym_k(float* __restrict__ xf, const float* __restrict__ delta) {
    int b = blockIdx.z;
    int j0 = blockIdx.x * 32, i0 = blockIdx.y * 32;
    int tx = threadIdx.x, ty = threadIdx.y;
    __shared__ float sh[32][33];
    size_t base = (size_t)b * NSQ;
    // load delta rows [j0, j0+32), cols [i0, i0+32) coalesced
    int lr = j0 + ty, lc = i0 + tx;
    sh[ty][tx] = (lr < NN && lc < NN) ? delta[base + (size_t)lr * NN + lc] : 0.f;
    __syncthreads();
    int i = i0 + ty, j = j0 + tx;
    if (i < NN && j < NN) {
        size_t idx = base + (size_t)i * NN + j;
        float v = xf[idx];
        if (i != j) v += 0.5f * (delta[idx] + sh[tx][ty]);   // sh[tx][ty] = delta[j][i]
        xf[idx] = v;
    }
}

// ---------------- exact k-th largest via 64-bit key radix select -------------
__device__ __forceinline__ unsigned long long make_key(float v, unsigned t) {
    unsigned u = __float_as_uint(v);
    unsigned k32 = (u & 0x80000000u) ? ~u : (u | 0x80000000u);
    return ((unsigned long long)k32 << 32) | (unsigned long long)(~t);
}

__global__ void radix_select_k(const float* __restrict__ x2,
                               unsigned long long* __restrict__ thresh) {
    const int b = blockIdx.x;
    const float* xp = x2 + (size_t)b * NSQ;
    __shared__ unsigned hist[16][256];
    __shared__ unsigned total[256];
    __shared__ unsigned long long s_prefix;
    __shared__ unsigned s_remaining;
    int tid = threadIdx.x;          // 512 threads = 16 warps
    int wid = tid >> 5, lane = tid & 31;
    if (tid == 0) { s_prefix = 0ull; s_remaining = KTOP; }
    __syncthreads();

    for (int pass = 0; pass < 8; pass++) {
        int shift = 56 - 8 * pass;
        for (int i = tid; i < 16 * 256; i += 512) ((unsigned*)hist)[i] = 0;
        __syncthreads();
        unsigned long long prefix = s_prefix;
        int hs = shift + 8;
        for (int t = tid; t < 160256; t += 512) {
            bool inr = t < NSQ;
            unsigned long long key = inr ? make_key(xp[t], (unsigned)t) : 0ull;
            bool ok = inr && ((hs >= 64) || ((key >> hs) == (prefix >> hs)));
            unsigned bin = (unsigned)((key >> shift) & 255);
            unsigned active = __ballot_sync(0xffffffffu, ok);
            if (ok) {
                unsigned peers = __match_any_sync(active, bin);
                int leader = __ffs(peers) - 1;
                if (lane == leader) atomicAdd(&hist[wid][bin], __popc(peers));
            }
        }
        __syncthreads();
        for (int i = tid; i < 256; i += 512) {
            unsigned s = 0;
            #pragma unroll
            for (int w = 0; w < 16; w++) s += hist[w][i];
            total[i] = s;
        }
        __syncthreads();
        if (tid == 0) {
            unsigned rem = s_remaining, cum = 0;
            int chosen = 0;
            for (int bin = 255; bin >= 0; bin--) {
                unsigned c = total[bin];
                if (cum + c >= rem) { chosen = bin; s_remaining = rem - cum; break; }
                cum += c;
            }
            s_prefix |= ((unsigned long long)chosen << shift);
        }
        __syncthreads();
    }
    if (tid == 0) thresh[b] = s_prefix;   // exact k-th largest (value, index) key
}

// ---------------- A = x2 * mask (+ self loops where diag==0) ----------------
__global__ void mask_k(const float* __restrict__ x2,
                       const unsigned long long* __restrict__ thresh,
                       float* __restrict__ A) {
    int r = blockIdx.x * 256 + threadIdx.x;
    int b = blockIdx.y;
    size_t idx = (size_t)b * NSQ + r;
    float v = x2[idx];
    unsigned long long key = make_key(v, (unsigned)r);
    float a = (key >= thresh[b]) ? v : 0.f;
    int i = r / NN, j = r - i * NN;
    if (i == j && a == 0.f) a = 1.f;
    A[idx] = a;
}

// ---------------- column degree -> dinv --------------------------------------
__global__ void deg_k(const float* __restrict__ A, float* __restrict__ dinv) {
    int b = blockIdx.x;
    int j = threadIdx.x;
    if (j >= NN) return;
    const float* Ab = A + (size_t)b * NSQ;
    float acc = 0.f;
    for (int i = 0; i < NN; i++) acc += Ab[(size_t)i * NN + j];
    float dv = rsqrtf(acc);
    if (isinf(dv)) dv = 0.f;
    dinv[b * NN + j] = dv;
}

// ---------------- An = dinv[i]*A*dinv[j] in place; rs[i] = sum_j An[i,j]/N ---
__global__ void an_k(float* __restrict__ A, const float* __restrict__ dinv,
                     float* __restrict__ rs) {
    int i = blockIdx.x, b = blockIdx.y;
    int tid = threadIdx.x;     // 128
    const float* dv = dinv + b * NN;
    float* row = A + (size_t)b * NSQ + (size_t)i * NN;
    float di = dv[i];
    float acc = 0.f;
    for (int j = tid; j < NN; j += 128) {
        float v = row[j] * di * dv[j];
        row[j] = v;
        acc += v;
    }
    __shared__ float sb[128];
    sb[tid] = acc;
    __syncthreads();
    for (int s = 64; s > 0; s >>= 1) {
        if (tid < s) sb[tid] += sb[tid + s];
        __syncthreads();
    }
    if (tid == 0) rs[b * NN + i] = sb[0] * (1.f / NN);
}

// ---------------- generic batched SMEM-tiled GEMM ----------------------------
// C[M,N] = A(MxK) @ B(KxN); TRANSA: A stored [K][M]; EPI 0=none,1=relu,2=relu+skip
// TRANSOUT: store C at [n*ldc + m]
#define BM 64
#define BN 64
#define BK 16

template<int TRANSA, int EPI, int TRANSOUT>
__global__ void gemm_k(const float* __restrict__ A, size_t strideA, int lda,
                       const float* __restrict__ Bm, size_t strideB, int ldb,
                       const float* __restrict__ bias,
                       const float* __restrict__ skip, size_t strideS, int lds,
                       float* __restrict__ C, size_t strideC, int ldc,
                       int M, int N, int K) {
    int b = blockIdx.z;
    A += (size_t)b * strideA;
    Bm += (size_t)b * strideB;
    if (EPI == 2) skip += (size_t)b * strideS;
    C += (size_t)b * strideC;

    int n0 = blockIdx.x * BN;
    int m0 = blockIdx.y * BM;

    __shared__ float As[BK][BM + 1];
    __shared__ float Bs[BK][BN];

    int tid = threadIdx.x;              // 256
    int tm = (tid / 16) * 4;
    int tn = (tid % 16) * 4;

    float acc[4][4] = {};

    for (int k0 = 0; k0 < K; k0 += BK) {
        if (TRANSA) {
            int kk = tid / 64, mm = tid % 64;
            #pragma unroll
            for (int r = 0; r < 4; r++) {
                int k = kk + r * 4;
                int m = m0 + mm;
                As[k][mm] = (m < M) ? A[(size_t)(k0 + k) * lda + m] : 0.f;
            }
        } else {
            int row = tid / 16, col = tid % 16;
            #pragma unroll
            for (int r = 0; r < 4; r++) {
                int m = m0 + row + r * 16;
                As[col][row + r * 16] = (m < M) ? A[(size_t)m * lda + (k0 + col)] : 0.f;
            }
        }
        {
            int kk = tid / 64, nn = tid % 64;
            #pragma unroll
            for (int r = 0; r < 4; r++) {
                int k = kk + r * 4;
                int n = n0 + nn;
                Bs[k][nn] = (n < N) ? Bm[(size_t)(k0 + k) * ldb + n] : 0.f;
            }
        }
        __syncthreads();
        #pragma unroll
        for (int k = 0; k < BK; k++) {
            float a[4], bv[4];
            #pragma unroll
            for (int i = 0; i < 4; i++) a[i] = As[k][tm + i];
            #pragma unroll
            for (int j = 0; j < 4; j++) bv[j] = Bs[k][tn + j];
            #pragma unroll
            for (int i = 0; i < 4; i++)
                #pragma unroll
                for (int j = 0; j < 4; j++)
                    acc[i][j] += a[i] * bv[j];
        }
        __syncthreads();
    }

    #pragma unroll
    for (int i = 0; i < 4; i++) {
        int m = m0 + tm + i;
        if (m >= M) continue;
        #pragma unroll
        for (int j = 0; j < 4; j++) {
            int n = n0 + tn + j;
            if (n >= N) continue;
            float v = acc[i][j];
            if (bias) v += bias[n];
            if (EPI == 2) v += skip[(size_t)m * lds + n];
            if (EPI >= 1) v = fmaxf(v, 0.f);
            if (TRANSOUT) C[(size_t)n * ldc + m] = v;
            else          C[(size_t)m * ldc + n] = v;
        }
    }
}

// ---------------- head: pooled = rs . Y2 + b; out = relu(pooled) @ fc --------
__global__ void head_k(const float* __restrict__ Y2, const float* __restrict__ rs,
                       const float* __restrict__ b2, const float* __restrict__ fcw,
                       const float* __restrict__ fcb, float* __restrict__ out) {
    int b = blockIdx.x;
    int f = threadIdx.x;                // 128
    const float* Y = Y2 + (size_t)b * (NN * HH);
    const float* r = rs + b * NN;
    float acc = 0.f;
    for (int i = 0; i < NN; i++) acc += r[i] * Y[(size_t)i * HH + f];
    acc += b2[f];
    float pf = fmaxf(acc, 0.f);
    __shared__ float sp[HH];
    sp[f] = pf;
    __syncthreads();
    if (f < 2) {
        float o = fcb[f];
        for (int q = 0; q < HH; q++) o += sp[q] * fcw[q * 2 + f];
        out[b * 2 + f] = o;
    }
}

// -----------------------------------------------------------------------------
extern "C" void kernel_launch(void* const* d_in, const int* in_sizes, int n_in,
                              void* d_out, int out_size) {
    const float* x      = (const float*)d_in[0];
    // d_in[1] = slength (unused)
    const float* enc1_w = (const float*)d_in[2];
    const float* enc1_b = (const float*)d_in[3];
    const float* enc2_w = (const float*)d_in[4];
    const float* enc2_b = (const float*)d_in[5];
    const float* dec2_w = (const float*)d_in[6];
    const float* dec2_b = (const float*)d_in[7];
    const float* dec1_w = (const float*)d_in[8];
    const float* dec1_b = (const float*)d_in[9];
    const float* gcn1_w = (const float*)d_in[10];
    const float* gcn1_b = (const float*)d_in[11];
    const float* gcn2_w = (const float*)d_in[12];
    const float* gcn2_b = (const float*)d_in[13];
    const float* fc_w   = (const float*)d_in[14];
    const float* fc_b   = (const float*)d_in[15];
    float* out = (float*)d_out;

    float *xf, *delta, *out1, *out2a, *out2, *h1, *dinv, *rs;
    unsigned long long* thresh;
    cudaGetSymbolAddress((void**)&xf, g_xf);
    cudaGetSymbolAddress((void**)&delta, g_delta);
    cudaGetSymbolAddress((void**)&out1, g_out1);
    cudaGetSymbolAddress((void**)&out2a, g_out2a);
    cudaGetSymbolAddress((void**)&out2, g_out2);
    cudaGetSymbolAddress((void**)&h1, g_h1);
    cudaGetSymbolAddress((void**)&thresh, g_thresh);
    cudaGetSymbolAddress((void**)&dinv, g_dinv);
    cudaGetSymbolAddress((void**)&rs, g_rs);

    const size_t S_NN = (size_t)NSQ;          // 160000
    const size_t S_HN = (size_t)HH * NN;      // 51200
    const size_t S_HH = (size_t)HH * HH;      // 16384

    // 0) fisher transform + normalize
    fisher_k<<<dim3(625, BATCH), 256>>>(x, xf);

    // 1) out1[b,h,i] = relu(xf @ enc1_w + b)  (transposed store)
    gemm_k<0, 1, 1><<<dim3(2, 7, BATCH), 256>>>(
        xf, S_NN, NN, enc1_w, 0, HH, enc1_b, nullptr, 0, 0,
        out1, S_HN, NN, NN, HH, NN);

    // 2) out2a = relu(out1 @ enc2_w + b)   [B,H,H]
    gemm_k<0, 1, 0><<<dim3(2, 2, BATCH), 256>>>(
        out1, S_HN, NN, enc2_w, 0, HH, enc2_b, nullptr, 0, 0,
        out2a, S_HH, HH, HH, HH, NN);

    // 3) out2 = relu(out2a @ dec2_w + b + out1)  [B,H,N]
    gemm_k<0, 2, 0><<<dim3(7, 2, BATCH), 256>>>(
        out2a, S_HH, HH, dec2_w, 0, NN, dec2_b, out1, S_HN, NN,
        out2, S_HN, NN, HH, NN, HH);

    // 4) delta = out2^T @ dec1_w + b  [B,N,N]
    gemm_k<1, 0, 0><<<dim3(7, 7, BATCH), 256>>>(
        out2, S_HN, NN, dec1_w, 0, NN, dec1_b, nullptr, 0, 0,
        delta, S_NN, NN, NN, NN, HH);

    // 5) x2 = xf + 0.5*(delta + delta^T)*(1-eye)  (in place in xf)
    sym_k<<<dim3(13, 13, BATCH), dim3(32, 32)>>>(xf, delta);

    // 6) per-batch exact top-k threshold key
    radix_select_k<<<BATCH, 512>>>(xf, thresh);

    // 7) A = masked x2 (+ self loops), into delta buffer
    mask_k<<<dim3(625, BATCH), 256>>>(xf, thresh, delta);

    // 8) column degrees -> dinv
    deg_k<<<BATCH, 512>>>(delta, dinv);

    // 9) An = dinv_i * A * dinv_j in place; rs = row means
    an_k<<<dim3(NN, BATCH), 128>>>(delta, dinv, rs);

    // 10) Y1 = x2 @ gcn1_w   [B,N,H]  (into out2 buffer)
    gemm_k<0, 0, 0><<<dim3(2, 7, BATCH), 256>>>(
        xf, S_NN, NN, gcn1_w, 0, HH, nullptr, nullptr, 0, 0,
        out2, S_HN, HH, NN, HH, NN);

    // 11) h1 = relu(An^T @ Y1 + gcn1_b)  [B,N,H]
    gemm_k<1, 1, 0><<<dim3(2, 7, BATCH), 256>>>(
        delta, S_NN, NN, out2, S_HN, HH, gcn1_b, nullptr, 0, 0,
        h1, S_HN, HH, NN, HH, NN);

    // 12) Y2 = h1 @ gcn2_w  [B,N,H] (into out1 buffer)
    gemm_k<0, 0, 0><<<dim3(2, 7, BATCH), 256>>>(
        h1, S_HN, HH, gcn2_w, 0, HH, nullptr, nullptr, 0, 0,
        out1, S_HN, HH, NN, HH, HH);

    // 13) pooled/head: mean_j(An^T Y2 + b2) folded to rs . Y2 + b2, then fc
    head_k<<<BATCH, HH>>>(out1, rs, gcn2_b, fc_w, fc_b, out);
}